// round 14
// baseline (speedup 1.0000x reference)
#include <cuda_runtime.h>
#include <cuda_fp16.h>
#include <math.h>
#include <stdint.h>

// ---------------- problem constants ----------------
#define BB   128      // batch
#define TT   512      // triples per dialogue
#define LQ   256      // query length
#define NN   256      // nodes per dialogue
#define DN   100      // node dim
#define DH   300      // hidden dim
#define EPS  1e-5f

#define M_BT (BB*TT)          // 65536
#define M_BN (BB*NN)          // 32768

// padded K dims (multiples of 8 halves = 16B)
#define P_DN   104
#define P_DH   304
#define P_2DH  608

// fused-GRU GEMM output width: 600 hidden cols x 4 slots (r,z,n,pad), 19 tiles
#define N_GI   2432

// ---------------- device scratch (static globals; no allocation) ----------------
__device__ __half g_tri_h  [(long)M_BT * P_DN];       // 13.6 MB
__device__ float  g_scores [(long)BB * LQ * TT];      // 67 MB
__device__ __half g_hidden_h[(long)M_BT * P_2DH];     // 79.7 MB
__device__ __half g_hid_h  [(long)M_BT * P_DH];       // 39.8 MB
__device__ __half g_ctx_h  [(long)BB * LQ * P_DH];    // 19.9 MB
__device__ __half g_nodes_h[(long)M_BN * P_DN];       //  6.8 MB
__device__ __half g_wc_h   [N_GI * P_DN];             // gate-interleaved fused weight
__device__ float  g_b1     [N_GI];                    // per-slot bias (bhh folded for r,z)
__device__ float  g_b2     [P_2DH];                   // b_hh_n per hidden col
__device__ __half g_wout_h [DH * P_2DH];
__device__ __half g_wnode_h[DH * P_DN];
__device__ float  g_alpha  [(long)BB * TT];
__device__ float  g_zero_bias[2048];                  // zero-initialized

// =======================================================================
// fp16 mma.sync GEMM (m16n8k16, fp32 accum), cp.async 3-stage pipeline.
//   C[M,N] = A[M,Kpad] * B[N,Kpad]^T  (+bias; opt tanh; half/float out)
// GRU variant: N = N_GI gate-interleaved; epilogue computes the GRU gate
// activation on fp32 accumulators and stores hidden[M, P_2DH] (half) directly.
// CTA tile 128x128, BK=32 halves, 256 threads (8 warps 2x4), warp 64x32.
// grid.x = N tiles (fast), grid.y = M tiles. M % 128 == 0.
// =======================================================================

#define HSTR 40                    // halves per smem row (conflict-free)
#define HBUF (128 * HSTR)          // 5120 halves per tile buffer
#define GEMM_SMEM (6 * HBUF * 2)   // 3 A bufs + 3 B bufs = 61440 bytes

__device__ __forceinline__ float sigf(float x) { return 1.f / (1.f + expf(-x)); }

template<bool TANH, bool HALF_OUT, bool GRU>
__global__ void __launch_bounds__(256)
mma_gemm_kernel(const __half* __restrict__ A, const __half* __restrict__ Bm,
                const float* __restrict__ bias, const float* __restrict__ bias2,
                void* __restrict__ Cv,
                int M, int N, int Kpad, int lda, int ldb, int ldc,
                long strideA, long strideB, long strideC)
{
    extern __shared__ __half hsm[];   // [3][128][HSTR] A, then [3][128][HSTR] B

    const int batch = blockIdx.z;
    A  += (long)batch * strideA;
    Bm += (long)batch * strideB;

    const int tid   = threadIdx.x;           // 0..255
    const int wid   = tid >> 5;
    const int lane  = tid & 31;
    const int warpM = wid >> 2;              // 0..1
    const int warpN = wid & 3;               // 0..3
    const int g     = lane >> 2;             // 0..7
    const int t4    = lane & 3;              // 0..3

    const int rowBase = blockIdx.y * 128;
    const int colBase = blockIdx.x * 128;

    const int fr = tid >> 2;                 // 0..63
    const int fq = tid & 3;                  // 16B chunk in 64B row

    float c[4][4][4];
    #pragma unroll
    for (int mt = 0; mt < 4; mt++)
        #pragma unroll
        for (int nt = 0; nt < 4; nt++)
            #pragma unroll
            for (int q = 0; q < 4; q++) c[mt][nt][q] = 0.f;

    const int nStages = (Kpad + 31) / 32;

    auto load_stage = [&](int s) {
        const int buf = s % 3;
        __half* as = hsm + buf * HBUF;
        __half* bs = hsm + (3 + buf) * HBUF;
        const int gk = s * 32 + fq * 8;      // half index
        #pragma unroll
        for (int it = 0; it < 2; it++) {
            int r = fr + it * 64;
            {
                uint32_t dst = (uint32_t)__cvta_generic_to_shared(&as[r * HSTR + fq * 8]);
                const __half* src = (gk < Kpad) ? &A[(long)(rowBase + r) * lda + gk] : A;
                int sz = (gk < Kpad) ? 16 : 0;
                asm volatile("cp.async.ca.shared.global [%0], [%1], 16, %2;"
                             :: "r"(dst), "l"(src), "r"(sz));
            }
            {
                int gn = colBase + r;
                bool ok = (gn < N) && (gk < Kpad);
                uint32_t dst = (uint32_t)__cvta_generic_to_shared(&bs[r * HSTR + fq * 8]);
                const __half* src = ok ? &Bm[(long)gn * ldb + gk] : Bm;
                int sz = ok ? 16 : 0;
                asm volatile("cp.async.ca.shared.global [%0], [%1], 16, %2;"
                             :: "r"(dst), "l"(src), "r"(sz));
            }
        }
        asm volatile("cp.async.commit_group;");
    };

    load_stage(0);
    if (nStages > 1) load_stage(1);

    for (int s = 0; s < nStages; s++) {
        if (s + 1 < nStages) asm volatile("cp.async.wait_group 1;");
        else                 asm volatile("cp.async.wait_group 0;");
        __syncthreads();

        const __half* as = hsm + (s % 3) * HBUF;
        const __half* bs = hsm + (3 + s % 3) * HBUF;

        #pragma unroll
        for (int kk = 0; kk < 32; kk += 16) {
            uint32_t ar[4][4], br[4][2];
            #pragma unroll
            for (int mt = 0; mt < 4; mt++) {
                int r0 = warpM * 64 + mt * 16 + g;
                ar[mt][0] = *reinterpret_cast<const uint32_t*>(&as[(r0    ) * HSTR + kk + 2 * t4    ]);
                ar[mt][1] = *reinterpret_cast<const uint32_t*>(&as[(r0 + 8) * HSTR + kk + 2 * t4    ]);
                ar[mt][2] = *reinterpret_cast<const uint32_t*>(&as[(r0    ) * HSTR + kk + 2 * t4 + 8]);
                ar[mt][3] = *reinterpret_cast<const uint32_t*>(&as[(r0 + 8) * HSTR + kk + 2 * t4 + 8]);
            }
            #pragma unroll
            for (int nt = 0; nt < 4; nt++) {
                int n0 = warpN * 32 + nt * 8 + g;
                br[nt][0] = *reinterpret_cast<const uint32_t*>(&bs[n0 * HSTR + kk + 2 * t4    ]);
                br[nt][1] = *reinterpret_cast<const uint32_t*>(&bs[n0 * HSTR + kk + 2 * t4 + 8]);
            }
            #pragma unroll
            for (int mt = 0; mt < 4; mt++)
                #pragma unroll
                for (int nt = 0; nt < 4; nt++) {
                    asm volatile(
                        "mma.sync.aligned.m16n8k16.row.col.f32.f16.f16.f32 "
                        "{%0,%1,%2,%3}, {%4,%5,%6,%7}, {%8,%9}, {%0,%1,%2,%3};"
                        : "+f"(c[mt][nt][0]), "+f"(c[mt][nt][1]),
                          "+f"(c[mt][nt][2]), "+f"(c[mt][nt][3])
                        : "r"(ar[mt][0]), "r"(ar[mt][1]), "r"(ar[mt][2]), "r"(ar[mt][3]),
                          "r"(br[nt][0]), "r"(br[nt][1]));
                }
        }
        if (s + 2 < nStages) load_stage(s + 2);
    }

    if (GRU) {
        // cols 4*jg+{0,1,2,3} = (r, z, n, pad). Even-t4 threads hold (r,z);
        // odd-t4 neighbor holds n. Combine via shfl, apply GRU gate math,
        // store hidden[row, jg] (half).
        __half* Ch = (__half*)Cv;
        #pragma unroll
        for (int mt = 0; mt < 4; mt++) {
            int r0 = rowBase + warpM * 64 + mt * 16 + g;
            #pragma unroll
            for (int nt = 0; nt < 4; nt++) {
                int col0 = colBase + warpN * 32 + nt * 8 + 2 * t4;
                float nAcc0 = __shfl_xor_sync(0xffffffffu, c[mt][nt][0], 1);
                float nAcc1 = __shfl_xor_sync(0xffffffffu, c[mt][nt][2], 1);
                if ((t4 & 1) == 0) {
                    int jg = col0 >> 2;
                    float br = bias[col0], bz = bias[col0 + 1], bn = bias[col0 + 2];
                    float b2v = bias2[jg];
                    float r  = sigf(c[mt][nt][0] + br);
                    float z  = sigf(c[mt][nt][1] + bz);
                    float h0 = (1.f - z) * tanhf(nAcc0 + bn + r * b2v);
                    r  = sigf(c[mt][nt][2] + br);
                    z  = sigf(c[mt][nt][3] + bz);
                    float h1 = (1.f - z) * tanhf(nAcc1 + bn + r * b2v);
                    if (jg >= 2 * DH) { h0 = 0.f; h1 = 0.f; }   // pad cols 600..607
                    Ch[(long)r0 * ldc + jg]       = __float2half_rn(h0);
                    Ch[(long)(r0 + 8) * ldc + jg] = __float2half_rn(h1);
                }
            }
        }
        return;
    }

    // ---- standard epilogue ----
    __half* Ch = (__half*)Cv + (HALF_OUT ? (long)batch * strideC : 0);
    float*  Cf = (float*)Cv + (HALF_OUT ? 0 : (long)batch * strideC);

    #pragma unroll
    for (int mt = 0; mt < 4; mt++) {
        int r0 = rowBase + warpM * 64 + mt * 16 + g;
        #pragma unroll
        for (int nt = 0; nt < 4; nt++) {
            int col0 = colBase + warpN * 32 + nt * 8 + 2 * t4;
            if (col0 + 1 < N) {
                float b0 = bias[col0], b1 = bias[col0 + 1];
                float v00 = c[mt][nt][0] + b0, v01 = c[mt][nt][1] + b1;
                float v10 = c[mt][nt][2] + b0, v11 = c[mt][nt][3] + b1;
                if (TANH) {
                    v00 = tanhf(v00); v01 = tanhf(v01);
                    v10 = tanhf(v10); v11 = tanhf(v11);
                }
                if (HALF_OUT) {
                    *reinterpret_cast<__half2*>(&Ch[(long)r0 * ldc + col0]) =
                        __floats2half2_rn(v00, v01);
                    *reinterpret_cast<__half2*>(&Ch[(long)(r0 + 8) * ldc + col0]) =
                        __floats2half2_rn(v10, v11);
                } else {
                    *reinterpret_cast<float2*>(&Cf[(long)r0 * ldc + col0]) = make_float2(v00, v01);
                    *reinterpret_cast<float2*>(&Cf[(long)(r0 + 8) * ldc + col0]) = make_float2(v10, v11);
                }
            } else {
                #pragma unroll
                for (int s2 = 0; s2 < 2; s2++) {
                    int cc = col0 + s2;
                    if (HALF_OUT) {
                        if (cc < ldc) {
                            float v0 = 0.f, v1 = 0.f;
                            if (cc < N) {
                                float bb = bias[cc];
                                v0 = c[mt][nt][0 + s2] + bb;
                                v1 = c[mt][nt][2 + s2] + bb;
                                if (TANH) { v0 = tanhf(v0); v1 = tanhf(v1); }
                            }
                            Ch[(long)r0 * ldc + cc] = __float2half_rn(v0);
                            Ch[(long)(r0 + 8) * ldc + cc] = __float2half_rn(v1);
                        }
                    } else {
                        if (cc < N) {
                            float bb = bias[cc];
                            float v0 = c[mt][nt][0 + s2] + bb;
                            float v1 = c[mt][nt][2 + s2] + bb;
                            if (TANH) { v0 = tanhf(v0); v1 = tanhf(v1); }
                            Cf[(long)r0 * ldc + cc] = v0;
                            Cf[(long)(r0 + 8) * ldc + cc] = v1;
                        }
                    }
                }
            }
        }
    }
}

// ---------------- fused + gate-interleaved weight ----------------
// Wc'[col, d] for col = 4*jg + gate: row (dir*900 + gate*300 + j) of Wih @ W_mean.
__global__ void wc_weight_kernel(const float* __restrict__ Wf,
                                 const float* __restrict__ Wb,
                                 const float* __restrict__ Wm,
                                 __half* __restrict__ Wc)
{
    int idx = blockIdx.x * blockDim.x + threadIdx.x;   // over N_GI * P_DN
    if (idx >= N_GI * P_DN) return;
    int d   = idx % P_DN;
    int col = idx / P_DN;
    int jg = col >> 2, gate = col & 3;
    __half h = __float2half_rn(0.f);
    if (d < DN && gate < 3 && jg < 2 * DH) {
        int dir = jg / DH, j = jg % DH;
        int row = gate * DH + j;
        const float* wr = dir ? &Wb[(long)row * DH] : &Wf[(long)row * DH];
        float acc = 0.f;
        #pragma unroll 4
        for (int k = 0; k < DH; k++) acc = fmaf(wr[k], Wm[k * DN + d], acc);
        h = __float2half_rn(acc);
    }
    Wc[idx] = h;
}

// ---------------- fused biases ----------------
// b1[4*jg+gate] = b_ih[row] + Wih[row]@b_mean  (+ b_hh[row] for r,z gates)
// b2[jg] = b_hh[dir][2*DH + j]   (the n-gate hidden bias, multiplied by r)
__global__ void b12_kernel(const float* __restrict__ Wf, const float* __restrict__ Wb,
                           const float* __restrict__ bm,
                           const float* __restrict__ bihf, const float* __restrict__ bihb,
                           const float* __restrict__ bhhf, const float* __restrict__ bhhb,
                           float* __restrict__ b1, float* __restrict__ b2)
{
    int i = blockIdx.x * blockDim.x + threadIdx.x;
    if (i >= N_GI) return;
    int jg = i >> 2, gate = i & 3;
    float v = 0.f;
    if (gate < 3 && jg < 2 * DH) {
        int dir = jg / DH, j = jg % DH;
        int row = gate * DH + j;
        const float* wr  = dir ? &Wb[(long)row * DH] : &Wf[(long)row * DH];
        const float* bih = dir ? bihb : bihf;
        const float* bhh = dir ? bhhb : bhhf;
        float acc = bih[row];
        for (int k = 0; k < DH; k++) acc = fmaf(wr[k], bm[k], acc);
        if (gate < 2) acc += bhh[row];     // fold b_hh for r,z
        v = acc;
    }
    b1[i] = v;
    if (gate == 3) {
        float v2 = 0.f;
        if (jg < 2 * DH) {
            int dir = jg / DH, j = jg % DH;
            const float* bhh = dir ? bhhb : bhhf;
            v2 = bhh[2 * DH + j];
        }
        if (jg < P_2DH) b2[jg] = v2;
    }
}

// ---------------- fp32 -> padded fp16 convert ----------------
__global__ void f2h_pad_kernel(const float* __restrict__ src, __half* __restrict__ dst,
                               long rows, int K, int Kpad)
{
    long n2 = rows * (Kpad / 2);
    long i = (long)blockIdx.x * blockDim.x + threadIdx.x;
    if (i >= n2) return;
    int  c2 = (int)(i % (Kpad / 2));
    long r  = i / (Kpad / 2);
    int col = 2 * c2;
    __half2 h;
    if (col < K) {
        float2 v = *reinterpret_cast<const float2*>(&src[r * K + col]);
        h = __floats2half2_rn(v.x, v.y);
    } else {
        h = __floats2half2_rn(0.f, 0.f);
    }
    *reinterpret_cast<__half2*>(&dst[r * Kpad + col]) = h;
}

// ---------------- gather + mean, padded fp16 out ----------------
__global__ void gather_mean_kernel(const float* __restrict__ nodes,
                                   const int* __restrict__ trip,
                                   __half* __restrict__ out)
{
    long total = (long)M_BT * (P_DN / 2);
    long idx = (long)blockIdx.x * blockDim.x + threadIdx.x;
    if (idx >= total) return;
    int  c2 = (int)(idx % (P_DN / 2));
    long bt = idx / (P_DN / 2);
    int col = 2 * c2;
    int b = (int)(bt / TT);
    __half2 o;
    if (col < DN) {
        int h  = trip[bt * 3 + 0];
        int tl = trip[bt * 3 + 2];
        float2 vh = *reinterpret_cast<const float2*>(&nodes[((long)b * NN + h)  * DN + col]);
        float2 vt = *reinterpret_cast<const float2*>(&nodes[((long)b * NN + tl) * DN + col]);
        o = __floats2half2_rn(0.5f * (vh.x + vt.x), 0.5f * (vh.y + vt.y));
    } else {
        o = __floats2half2_rn(0.f, 0.f);
    }
    *reinterpret_cast<__half2*>(&out[bt * P_DN + col]) = o;
}

// ---------------- per-row softmax + atomic alpha accumulation ----------------
__global__ void softmax_row_kernel(const float* __restrict__ S,
                                   float* __restrict__ alpha)
{
    int l = blockIdx.x, b = blockIdx.y;
    int t = threadIdx.x;                 // 0..511
    __shared__ float red[16];
    __shared__ float bcast;
    const float* row = S + ((long)b * LQ + l) * TT;
    float s = row[t];

    float m = s;
    #pragma unroll
    for (int o = 16; o > 0; o >>= 1) m = fmaxf(m, __shfl_xor_sync(0xffffffffu, m, o));
    if ((t & 31) == 0) red[t >> 5] = m;
    __syncthreads();
    if (t < 16) {
        float v = red[t];
        #pragma unroll
        for (int o = 8; o > 0; o >>= 1) v = fmaxf(v, __shfl_xor_sync(0xffffu, v, o));
        if (t == 0) bcast = v;
    }
    __syncthreads();
    float bm = bcast;

    float e = expf(s - bm);
    float sm = e;
    #pragma unroll
    for (int o = 16; o > 0; o >>= 1) sm += __shfl_xor_sync(0xffffffffu, sm, o);
    if ((t & 31) == 0) red[t >> 5] = sm;
    __syncthreads();
    if (t < 16) {
        float v = red[t];
        #pragma unroll
        for (int o = 8; o > 0; o >>= 1) v += __shfl_xor_sync(0xffffu, v, o);
        if (t == 0) bcast = v;
    }
    __syncthreads();
    float tot = bcast;

    atomicAdd(&alpha[(long)b * TT + t], e / tot);
}

// ---------------- rep = alpha @ hid(half), then LayerNorm -> path_feature ------
__global__ void rep_ln_kernel(const __half* __restrict__ hid,
                              const float* __restrict__ alpha,
                              const float* __restrict__ gamma,
                              const float* __restrict__ beta,
                              float* __restrict__ out)
{
    int b = blockIdx.x;
    int tid = threadIdx.x;        // 512
    __shared__ float a_s[TT];
    __shared__ float r_s[DH];
    __shared__ float red[32];
    a_s[tid] = alpha[(long)b * TT + tid];
    __syncthreads();
    if (tid < DH) {
        const __half* hb = hid + (long)b * TT * P_DH;
        float v0 = 0.f, v1 = 0.f, v2 = 0.f, v3 = 0.f;
        #pragma unroll 1
        for (int t = 0; t < TT; t += 4) {
            v0 = fmaf(a_s[t + 0], __half2float(hb[(long)(t + 0) * P_DH + tid]), v0);
            v1 = fmaf(a_s[t + 1], __half2float(hb[(long)(t + 1) * P_DH + tid]), v1);
            v2 = fmaf(a_s[t + 2], __half2float(hb[(long)(t + 2) * P_DH + tid]), v2);
            v3 = fmaf(a_s[t + 3], __half2float(hb[(long)(t + 3) * P_DH + tid]), v3);
        }
        r_s[tid] = (v0 + v1) + (v2 + v3);
    }
    __syncthreads();
    float p  = (tid < DH) ? r_s[tid] : 0.f;
    float p2 = p * p;
    #pragma unroll
    for (int o = 16; o > 0; o >>= 1) {
        p  += __shfl_xor_sync(0xffffffffu, p,  o);
        p2 += __shfl_xor_sync(0xffffffffu, p2, o);
    }
    if ((tid & 31) == 0) { red[tid >> 5] = p; red[16 + (tid >> 5)] = p2; }
    __syncthreads();
    float mean = 0.f, m2 = 0.f;
    #pragma unroll
    for (int w = 0; w < 16; w++) { mean += red[w]; m2 += red[16 + w]; }
    mean /= (float)DH; m2 /= (float)DH;
    float var = m2 - mean * mean;
    if (tid < DH)
        out[(long)b * DH + tid] =
            (r_s[tid] - mean) * rsqrtf(var + EPS) * gamma[tid] + beta[tid];
}

// ---------------- zero-fill ----------------
__global__ void zero_kernel(float* __restrict__ p, long n)
{
    long i = (long)blockIdx.x * blockDim.x + threadIdx.x;
    if (i < n) p[i] = 0.f;
}

// ---------------- host launcher ----------------
extern "C" void kernel_launch(void* const* d_in, const int* in_sizes, int n_in,
                              void* d_out, int out_size)
{
    const float* nodes   = (const float*)d_in[0];
    const float* ctx     = (const float*)d_in[1];
    const int*   trip    = (const int*)  d_in[2];
    // d_in[3] = node_number (compile-time constant NN = 256)
    const float* W_mean  = (const float*)d_in[4];
    const float* b_mean  = (const float*)d_in[5];
    const float* W_ih_f  = (const float*)d_in[6];
    const float* b_ih_f  = (const float*)d_in[7];
    const float* b_hh_f  = (const float*)d_in[8];
    const float* W_ih_b  = (const float*)d_in[9];
    const float* b_ih_b  = (const float*)d_in[10];
    const float* b_hh_b  = (const float*)d_in[11];
    const float* W_out   = (const float*)d_in[12];
    const float* b_out   = (const float*)d_in[13];
    const float* W_node  = (const float*)d_in[14];
    const float* b_node  = (const float*)d_in[15];
    const float* gamma   = (const float*)d_in[16];
    const float* beta    = (const float*)d_in[17];
    float* out = (float*)d_out;

    __half *p_tri, *p_hiddenh, *p_hidh, *p_ctxh, *p_nodesh;
    __half *p_wc, *p_wout, *p_wnode;
    float *p_scores, *p_alpha, *p_b1, *p_b2, *p_zb;
    cudaGetSymbolAddress((void**)&p_tri,     g_tri_h);
    cudaGetSymbolAddress((void**)&p_scores,  g_scores);
    cudaGetSymbolAddress((void**)&p_hiddenh, g_hidden_h);
    cudaGetSymbolAddress((void**)&p_hidh,    g_hid_h);
    cudaGetSymbolAddress((void**)&p_ctxh,    g_ctx_h);
    cudaGetSymbolAddress((void**)&p_nodesh,  g_nodes_h);
    cudaGetSymbolAddress((void**)&p_wc,      g_wc_h);
    cudaGetSymbolAddress((void**)&p_b1,      g_b1);
    cudaGetSymbolAddress((void**)&p_b2,      g_b2);
    cudaGetSymbolAddress((void**)&p_wout,    g_wout_h);
    cudaGetSymbolAddress((void**)&p_wnode,   g_wnode_h);
    cudaGetSymbolAddress((void**)&p_alpha,   g_alpha);
    cudaGetSymbolAddress((void**)&p_zb,      g_zero_bias);

    cudaFuncSetAttribute(mma_gemm_kernel<false, true, true>,
                         cudaFuncAttributeMaxDynamicSharedMemorySize, GEMM_SMEM);
    cudaFuncSetAttribute(mma_gemm_kernel<true, true, false>,
                         cudaFuncAttributeMaxDynamicSharedMemorySize, GEMM_SMEM);
    cudaFuncSetAttribute(mma_gemm_kernel<false, false, false>,
                         cudaFuncAttributeMaxDynamicSharedMemorySize, GEMM_SMEM);

    // 0a) fused gate-interleaved weight + biases
    {
        int n = N_GI * P_DN;
        wc_weight_kernel<<<(n + 255) / 256, 256>>>(W_ih_f, W_ih_b, W_mean, p_wc);
        b12_kernel<<<(N_GI + 255) / 256, 256>>>(W_ih_f, W_ih_b, b_mean,
                                                b_ih_f, b_ih_b, b_hh_f, b_hh_b,
                                                p_b1, p_b2);
    }
    // 0b) operand conversion to padded fp16
    auto conv = [&](const float* s, __half* d, long rows, int K, int Kp) {
        long n2 = rows * (Kp / 2);
        f2h_pad_kernel<<<(unsigned)((n2 + 255) / 256), 256>>>(s, d, rows, K, Kp);
    };
    conv(ctx,    p_ctxh,  (long)BB * LQ, DH, P_DH);
    conv(nodes,  p_nodesh, M_BN, DN, P_DN);
    conv(W_node, p_wnode, DH, DN, P_DN);
    conv(W_out,  p_wout,  DH, 2 * DH, P_2DH);

    // 1) tri_mean gather -> half padded
    {
        long total = (long)M_BT * (P_DN / 2);
        gather_mean_kernel<<<(unsigned)((total + 255) / 256), 256>>>(nodes, trip, p_tri);
    }
    // 2+3+4 fused) hidden = GRU_act(tri @ Wc'^T) directly  [65536, 608] half
    {
        dim3 g(N_GI / 128, M_BT / 128, 1);
        mma_gemm_kernel<false, true, true><<<g, 256, GEMM_SMEM>>>(
            p_tri, p_wc, p_b1, p_b2, p_hiddenh,
            M_BT, N_GI, P_DN, P_DN, P_DN, P_2DH, 0, 0, 0);
    }
    // 5) hid = tanh(hidden @ W_out^T + b_out)   [65536,300] Kpad=608 -> half [.,304]
    {
        dim3 g(3, M_BT / 128, 1);
        mma_gemm_kernel<true, true, false><<<g, 256, GEMM_SMEM>>>(
            p_hiddenh, p_wout, b_out, p_zb, p_hidh,
            M_BT, DH, P_2DH, P_2DH, P_2DH, P_DH, 0, 0, 0);
    }
    // 6) scores[b] = ctx[b] @ hid[b]^T   (batched M=256,N=512,Kpad=304) -> float
    {
        dim3 g(4, LQ / 128, BB);
        mma_gemm_kernel<false, false, false><<<g, 256, GEMM_SMEM>>>(
            p_ctxh, p_hidh, p_zb, p_zb, p_scores, LQ, TT, P_DH, P_DH, P_DH, TT,
            (long)LQ * P_DH, (long)TT * P_DH, (long)LQ * TT);
    }
    // 7) alpha = sum_l softmax_t(scores)
    {
        long an = (long)BB * TT;
        zero_kernel<<<(unsigned)((an + 255) / 256), 256>>>(p_alpha, an);
        dim3 g(LQ, BB);
        softmax_row_kernel<<<g, TT>>>(p_scores, p_alpha);
    }
    // 8) rep + LayerNorm -> path_feature (out offset 0)
    rep_ln_kernel<<<BB, TT>>>(p_hidh, p_alpha, gamma, beta, out);
    // 9) node_feature = nodes @ W_node^T + b_node -> float out at offset B*DH
    {
        dim3 g(3, M_BN / 128, 1);
        mma_gemm_kernel<false, false, false><<<g, 256, GEMM_SMEM>>>(
            p_nodesh, p_wnode, b_node, p_zb, out + (long)BB * DH,
            M_BN, DH, P_DN, P_DN, P_DN, DH, 0, 0, 0);
    }
    // 10) node_mask zeros, if the output buffer includes it
    {
        long mask_off = (long)BB * DH + (long)M_BN * DH;   // 9,868,800
        long mask_n   = (long)BB * NN;                     // 32,768
        if ((long)out_size >= mask_off + mask_n) {
            zero_kernel<<<(unsigned)((mask_n + 255) / 256), 256>>>(out + mask_off, mask_n);
        }
    }
}